// round 2
// baseline (speedup 1.0000x reference)
#include <cuda_runtime.h>
#include <stdint.h>

// ---------------------------------------------------------------------------
// LateralInhibition: per-batch top-k masking.
//   B = 8 rows, N = 4,194,304 elems/row, k = floor(0.1*N) = 419,430.
//   out = in where in is among the row's top-k values (ties -> smallest index).
//
// Algorithm: exact radix-select of the k-th largest 32-bit sortable key.
//   K1 zero scratch
//   K2 13-bit coarse histogram (smem-privatized)            read 128MB
//   K3 scan coarse hist -> boundary bin + rank-in-bin
//   K4 collect boundary-bin candidates (smem staged)        read 128MB
//   K5 radix-select exact threshold + tie index cutoff (per-row block)
//   K6 masked write                                         read+write 256MB
// ---------------------------------------------------------------------------

#define NBATCH 8
#define HBINS  8192          // 13-bit coarse bins (key >> 19)
#define CAP    262144        // per-row candidate capacity (expected ~60K)
#define SCAP   6000          // per-block smem staging capacity

__device__ unsigned int g_hist[NBATCH][HBINS];
__device__ unsigned int g_cnt [NBATCH];
__device__ unsigned int g_ckey[NBATCH][CAP];
__device__ unsigned int g_cidx[NBATCH][CAP];
__device__ unsigned int g_pref[NBATCH];   // boundary 13-bit bin
__device__ unsigned int g_krem[NBATCH];   // 1-based rank within boundary bin
__device__ unsigned int g_thr [NBATCH];   // exact threshold key
__device__ unsigned int g_cut [NBATCH];   // max included index among key==thr

// monotonic float -> uint key (larger float => larger key)
__device__ __forceinline__ unsigned int f2k(float f) {
    unsigned int u = __float_as_uint(f);
    return u ^ ((u >> 31) ? 0xFFFFFFFFu : 0x80000000u);
}

__global__ void k_zero() {
    int t = blockIdx.x * blockDim.x + threadIdx.x;
    int total = NBATCH * HBINS;
    for (int i = t; i < total; i += gridDim.x * blockDim.x)
        ((unsigned int*)g_hist)[i] = 0;
    if (t < NBATCH) g_cnt[t] = 0;
}

__global__ void k_hist(const float4* __restrict__ in, int nvec) {
    __shared__ unsigned int sh[HBINS];
    const int b = blockIdx.y;
    for (int i = threadIdx.x; i < HBINS; i += blockDim.x) sh[i] = 0;
    __syncthreads();
    const float4* p = in + (size_t)b * nvec;
    int per_block = nvec / gridDim.x;
    int start = blockIdx.x * per_block;
    int end   = start + per_block;
    for (int i = start + threadIdx.x; i < end; i += blockDim.x) {
        float4 v = p[i];
        atomicAdd(&sh[f2k(v.x) >> 19], 1u);
        atomicAdd(&sh[f2k(v.y) >> 19], 1u);
        atomicAdd(&sh[f2k(v.z) >> 19], 1u);
        atomicAdd(&sh[f2k(v.w) >> 19], 1u);
    }
    __syncthreads();
    for (int i = threadIdx.x; i < HBINS; i += blockDim.x) {
        unsigned int c = sh[i];
        if (c) atomicAdd(&g_hist[b][i], c);
    }
}

__global__ void k_scan(int k) {
    __shared__ unsigned int sh[HBINS];
    const int b = blockIdx.x;
    for (int i = threadIdx.x; i < HBINS; i += blockDim.x) sh[i] = g_hist[b][i];
    __syncthreads();
    if (threadIdx.x == 0) {
        unsigned int cum = 0;
        for (int j = HBINS - 1; j >= 0; j--) {
            unsigned int c = sh[j];
            if (cum + c >= (unsigned int)k) {
                g_pref[b] = (unsigned int)j;
                g_krem[b] = (unsigned int)k - cum;   // 1-based rank in bin
                break;
            }
            cum += c;
        }
    }
}

__global__ void k_cand(const float4* __restrict__ in, int nvec) {
    __shared__ unsigned int s_n, s_base;
    __shared__ unsigned int skey[SCAP];
    __shared__ unsigned int sidx[SCAP];
    const int b = blockIdx.y;
    const unsigned int pref = g_pref[b];
    if (threadIdx.x == 0) s_n = 0;
    __syncthreads();
    const float4* p = in + (size_t)b * nvec;
    int per_block = nvec / gridDim.x;
    int start = blockIdx.x * per_block;
    int end   = start + per_block;
    for (int i = start + threadIdx.x; i < end; i += blockDim.x) {
        float4 v = p[i];
        unsigned int kk[4] = { f2k(v.x), f2k(v.y), f2k(v.z), f2k(v.w) };
        #pragma unroll
        for (int j = 0; j < 4; j++) {
            if ((kk[j] >> 19) == pref) {
                unsigned int gi  = (unsigned int)i * 4u + (unsigned int)j;
                unsigned int pos = atomicAdd(&s_n, 1u);
                if (pos < SCAP) { skey[pos] = kk[j]; sidx[pos] = gi; }
                else {  // overflow fallback: direct global
                    unsigned int gp = atomicAdd(&g_cnt[b], 1u);
                    if (gp < CAP) { g_ckey[b][gp] = kk[j]; g_cidx[b][gp] = gi; }
                }
            }
        }
    }
    __syncthreads();
    if (threadIdx.x == 0) {
        unsigned int m = min(s_n, (unsigned int)SCAP);
        s_base = atomicAdd(&g_cnt[b], m);
        s_n = m;
    }
    __syncthreads();
    for (unsigned int i = threadIdx.x; i < s_n; i += blockDim.x) {
        unsigned int gp = s_base + i;
        if (gp < CAP) { g_ckey[b][gp] = skey[i]; g_cidx[b][gp] = sidx[i]; }
    }
}

__global__ void k_select() {
    __shared__ unsigned int hist[256];
    __shared__ unsigned int s_fixedval, s_fixedmask, s_rank, s_E;
    __shared__ unsigned int eq_idx[4096];
    __shared__ unsigned int s_neq, s_cut;
    const int b = blockIdx.x;
    const unsigned int n = min(g_cnt[b], (unsigned int)CAP);
    if (threadIdx.x == 0) {
        s_fixedval = 0; s_fixedmask = 0; s_rank = g_krem[b]; s_E = 0;
        s_neq = 0; s_cut = 0xFFFFFFFFu;
    }
    __syncthreads();

    // 3 radix-select rounds over low-19 bits: widths 8,8,3
    const int shifts[3] = { 11, 3, 0 };
    const int widths[3] = { 8, 8, 3 };
    for (int r = 0; r < 3; r++) {
        const int s = shifts[r];
        const unsigned int m = (1u << widths[r]) - 1u;
        for (int i = threadIdx.x; i < 256; i += blockDim.x) hist[i] = 0;
        __syncthreads();
        const unsigned int fm = s_fixedmask, fv = s_fixedval;
        for (unsigned int i = threadIdx.x; i < n; i += blockDim.x) {
            unsigned int low = g_ckey[b][i] & 0x7FFFFu;
            if ((low & fm) == fv) atomicAdd(&hist[(low >> s) & m], 1u);
        }
        __syncthreads();
        if (threadIdx.x == 0) {
            unsigned int cum = 0, rank = s_rank, sel = 0;
            for (int d = (int)m; d >= 0; d--) {
                unsigned int c = hist[d];
                if (cum + c >= rank) { sel = (unsigned int)d; s_rank = rank - cum; s_E = c; break; }
                cum += c;
            }
            s_fixedval  |= sel << s;
            s_fixedmask |= m   << s;
        }
        __syncthreads();
    }

    const unsigned int thr   = (g_pref[b] << 19) | s_fixedval;
    const unsigned int extra = s_rank;   // # equals to include (1-based)
    const unsigned int E     = s_E;      // total equals
    if (threadIdx.x == 0) g_thr[b] = thr;
    __syncthreads();

    if (extra < E) {
        // need smallest-index tie-break: gather equal-key indices
        for (unsigned int i = threadIdx.x; i < n; i += blockDim.x) {
            if (g_ckey[b][i] == thr) {
                unsigned int pos = atomicAdd(&s_neq, 1u);
                if (pos < 4096) eq_idx[pos] = g_cidx[b][i];
            }
        }
        __syncthreads();
        unsigned int ne = min(s_neq, 4096u);
        // cutoff = extra-th smallest equal index (indices are unique)
        for (unsigned int j = threadIdx.x; j < ne; j += blockDim.x) {
            unsigned int me = eq_idx[j], c = 0;
            for (unsigned int t = 0; t < ne; t++) if (eq_idx[t] <= me) c++;
            if (c == extra) s_cut = me;
        }
        __syncthreads();
    }
    if (threadIdx.x == 0) g_cut[b] = s_cut;
}

__global__ void k_write(const float4* __restrict__ in, float4* __restrict__ out,
                        int nvec) {
    const int b = blockIdx.y;
    const unsigned int thr = g_thr[b];
    const unsigned int cut = g_cut[b];
    const float4* p = in  + (size_t)b * nvec;
    float4*       q = out + (size_t)b * nvec;
    int per_block = nvec / gridDim.x;
    int start = blockIdx.x * per_block;
    int end   = start + per_block;
    for (int i = start + threadIdx.x; i < end; i += blockDim.x) {
        float4 v = p[i];
        unsigned int base = (unsigned int)i * 4u;
        float4 o;
        unsigned int k0 = f2k(v.x);
        unsigned int k1 = f2k(v.y);
        unsigned int k2 = f2k(v.z);
        unsigned int k3 = f2k(v.w);
        o.x = (k0 > thr || (k0 == thr && base + 0u <= cut)) ? v.x : 0.0f;
        o.y = (k1 > thr || (k1 == thr && base + 1u <= cut)) ? v.y : 0.0f;
        o.z = (k2 > thr || (k2 == thr && base + 2u <= cut)) ? v.z : 0.0f;
        o.w = (k3 > thr || (k3 == thr && base + 3u <= cut)) ? v.w : 0.0f;
        q[i] = o;
    }
}

extern "C" void kernel_launch(void* const* d_in, const int* in_sizes, int n_in,
                              void* d_out, int out_size) {
    (void)n_in; (void)out_size;
    const int total = in_sizes[0];           // 33,554,432
    const int N     = total / NBATCH;        // 4,194,304
    int k = (int)((double)N * 0.1);          // 419,430 (python int() truncation)
    if (k < 1) k = 1;
    const int nvec = N / 4;                  // 1,048,576 float4 per row

    const float4* in  = (const float4*)d_in[0];
    float4*       out = (float4*)d_out;

    dim3 gbig(64, NBATCH);

    k_zero  <<<64, 256>>>();
    k_hist  <<<gbig, 1024>>>(in, nvec);
    k_scan  <<<NBATCH, 1024>>>(k);
    k_cand  <<<gbig, 1024>>>(in, nvec);
    k_select<<<NBATCH, 1024>>>();
    k_write <<<gbig, 1024>>>(in, out, nvec);
}

// round 3
// speedup vs baseline: 1.1924x; 1.1924x over previous
#include <cuda_runtime.h>
#include <stdint.h>

// ---------------------------------------------------------------------------
// LateralInhibition: per-batch top-k masking (B=8, N=4,194,304, k=419,430).
//
// Fast path (2 heavy passes, 384MB traffic):
//   A: read 128MB. count v>HI per row; append window candidates (LO<v<=HI)
//      with smem staging; 1024-bin fine histogram of window elems only.
//   B: 8 tiny blocks: exact threshold + tie-index cutoff from fine hist +
//      candidate list. Sets g_fail if window assumptions violated.
//   W: masked write (read+write 256MB) + state reset for next replay.
//
// Fallback path (gated on g_fail, exact for ANY input): the verified R2
// pipeline (13-bit hist -> scan -> cand -> radix select). Early-exits when
// g_fail==0 (the deterministic bench input never triggers it).
// ---------------------------------------------------------------------------

#define NBATCH 8
#define FBBINS 8192          // fallback coarse bins (f2k key >> 19)
#define CAP    262144        // per-row candidate capacity (shared both paths)
#define SCAP   2048          // passA per-block smem staging
#define FSCAP  6000          // fallback cand per-block smem staging
#define FINE   1024          // fine histogram bins over window
#define MCAP   512           // max keys in boundary fine-bin (fast path)
#define LO_F   1.26f         // window low edge  (true thr ~ 1.2816 +- 0.0008)
#define HI_F   1.31f         // window high edge

__device__ unsigned int g_cnt [NBATCH];
__device__ unsigned int g_hi  [NBATCH];
__device__ unsigned int g_ckey[NBATCH][CAP];
__device__ unsigned int g_cidx[NBATCH][CAP];
__device__ unsigned int g_fhist[NBATCH][FINE];
__device__ unsigned int g_thr [NBATCH];     // f2k key of threshold
__device__ unsigned int g_cut [NBATCH];     // max included idx among ties
__device__ int          g_fail;
// fallback scratch
__device__ unsigned int g_hist13[NBATCH][FBBINS];
__device__ unsigned int g_pref[NBATCH];
__device__ unsigned int g_krem[NBATCH];

// monotonic float -> uint key (larger float => larger key)
__device__ __forceinline__ unsigned int f2k(float f) {
    unsigned int u = __float_as_uint(f);
    return u ^ (0x80000000u | (unsigned int)((int)u >> 31));
}

// ============================ FAST PATH ====================================

__global__ void k_passA(const float4* __restrict__ in, int nvec) {
    __shared__ unsigned int sh_hist[FINE];
    __shared__ unsigned int skey[SCAP], sidx[SCAP];
    __shared__ unsigned int s_n, s_base, s_hi;
    const int b = blockIdx.y;
    const unsigned int LOB = __float_as_uint(LO_F);
    for (int i = threadIdx.x; i < FINE; i += blockDim.x) sh_hist[i] = 0;
    if (threadIdx.x == 0) { s_n = 0; s_hi = 0; }
    __syncthreads();
    const float4* p = in + (size_t)b * nvec;
    int per_block = (nvec + gridDim.x - 1) / gridDim.x;
    int start = blockIdx.x * per_block;
    int end   = min(start + per_block, nvec);
    unsigned int myhi = 0;
    #pragma unroll 2
    for (int i = start + threadIdx.x; i < end; i += blockDim.x) {
        float4 v = p[i];
        float xs[4] = { v.x, v.y, v.z, v.w };
        #pragma unroll
        for (int j = 0; j < 4; j++) {
            float x = xs[j];
            myhi += (x > HI_F) ? 1u : 0u;
            if (x > LO_F && x <= HI_F) {
                unsigned int uv = __float_as_uint(x);
                atomicAdd(&sh_hist[(uv - LOB) >> 9], 1u);
                unsigned int gi  = (unsigned int)i * 4u + (unsigned int)j;
                unsigned int pos = atomicAdd(&s_n, 1u);
                if (pos < SCAP) { skey[pos] = uv; sidx[pos] = gi; }
                else {
                    unsigned int gp = atomicAdd(&g_cnt[b], 1u);
                    if (gp < CAP) { g_ckey[b][gp] = uv; g_cidx[b][gp] = gi; }
                }
            }
        }
    }
    // reduce hi-count: warp shfl then one smem atomic per warp
    #pragma unroll
    for (int o = 16; o > 0; o >>= 1) myhi += __shfl_down_sync(0xFFFFFFFFu, myhi, o);
    if ((threadIdx.x & 31) == 0) atomicAdd(&s_hi, myhi);
    __syncthreads();
    if (threadIdx.x == 0) {
        atomicAdd(&g_hi[b], s_hi);
        unsigned int m = min(s_n, (unsigned int)SCAP);
        s_base = atomicAdd(&g_cnt[b], m);
        s_n = m;
    }
    __syncthreads();
    for (unsigned int i = threadIdx.x; i < s_n; i += blockDim.x) {
        unsigned int gp = s_base + i;
        if (gp < CAP) { g_ckey[b][gp] = skey[i]; g_cidx[b][gp] = sidx[i]; }
    }
    for (int i = threadIdx.x; i < FINE; i += blockDim.x) {
        unsigned int c = sh_hist[i];
        if (c) atomicAdd(&g_fhist[b][i], c);
    }
}

__global__ void k_selectB(int k) {
    __shared__ unsigned int h[FINE];
    __shared__ unsigned int csum[32];
    __shared__ unsigned int s_bsel, s_r;
    __shared__ unsigned int s_key[MCAP];
    __shared__ unsigned int s_m, s_thr, s_extra, s_E;
    __shared__ unsigned int eq_idx[1024];
    __shared__ unsigned int s_neq, s_cut;
    const int b = blockIdx.x;
    const unsigned int n  = g_cnt[b];
    const unsigned int hi = g_hi[b];
    const unsigned int uk = (unsigned int)k;
    bool valid = (n <= CAP) && (hi < uk) && (hi + n >= uk);
    if (!valid) { if (threadIdx.x == 0) g_fail = 1; return; }
    const unsigned int rank = uk - hi;          // 1-based, descending, in window
    for (int i = threadIdx.x; i < FINE; i += blockDim.x) h[i] = g_fhist[b][i];
    if (threadIdx.x == 0) {
        s_m = 0; s_neq = 0; s_cut = 0xFFFFFFFFu;
        s_thr = 0; s_extra = 0; s_E = 0;
    }
    __syncthreads();
    if (threadIdx.x < 32) {
        unsigned int s = 0;
        #pragma unroll
        for (int j = 0; j < 32; j++) s += h[threadIdx.x * 32 + j];
        csum[threadIdx.x] = s;
    }
    __syncthreads();
    if (threadIdx.x == 0) {
        unsigned int cum = 0;
        int c = 31;
        for (; c > 0; c--) {
            if (cum + csum[c] >= rank) break;
            cum += csum[c];
        }
        int bsel = c * 32;
        for (int d = c * 32 + 31; d >= c * 32; d--) {
            if (cum + h[d] >= rank) { bsel = d; break; }
            cum += h[d];
        }
        s_bsel = (unsigned int)bsel;
        s_r    = rank - cum;
    }
    __syncthreads();
    const unsigned int bsel = s_bsel, r = s_r;
    const unsigned int LOB = __float_as_uint(LO_F);
    // gather boundary-bin keys
    for (unsigned int i = threadIdx.x; i < n; i += blockDim.x) {
        unsigned int uv = g_ckey[b][i];
        if (((uv - LOB) >> 9) == bsel) {
            unsigned int p = atomicAdd(&s_m, 1u);
            if (p < MCAP) s_key[p] = uv;
        }
    }
    __syncthreads();
    unsigned int m = s_m;
    if (m > MCAP) { if (threadIdx.x == 0) g_fail = 1; return; }
    // exact r-th largest among m keys (m ~ 45)
    for (unsigned int j = threadIdx.x; j < m; j += blockDim.x) {
        unsigned int x = s_key[j], cg = 0, ce = 0;
        for (unsigned int t = 0; t < m; t++) {
            unsigned int y = s_key[t];
            cg += (y > x); ce += (y == x);
        }
        if (cg < r && r <= cg + ce) { s_thr = x; s_extra = r - cg; s_E = ce; }
    }
    __syncthreads();
    const unsigned int thr = s_thr, extra = s_extra, E = s_E;
    if (extra < E) {   // tie-break: extra-th smallest index among equals
        for (unsigned int i = threadIdx.x; i < n; i += blockDim.x) {
            if (g_ckey[b][i] == thr) {
                unsigned int p = atomicAdd(&s_neq, 1u);
                if (p < 1024) eq_idx[p] = g_cidx[b][i];
            }
        }
        __syncthreads();
        unsigned int ne = s_neq;
        if (ne > 1024) { if (threadIdx.x == 0) g_fail = 1; return; }
        for (unsigned int j = threadIdx.x; j < ne; j += blockDim.x) {
            unsigned int me = eq_idx[j], c2 = 0;
            for (unsigned int t = 0; t < ne; t++) c2 += (eq_idx[t] <= me);
            if (c2 == extra) s_cut = me;
        }
        __syncthreads();
    }
    if (threadIdx.x == 0) {
        g_thr[b] = thr | 0x80000000u;   // f2k of a positive float
        g_cut[b] = s_cut;
    }
}

// ========================= FALLBACK (gated) ================================

__global__ void fb_zero() {
    if (!g_fail) return;
    int t = blockIdx.x * blockDim.x + threadIdx.x;
    int total = NBATCH * FBBINS;
    for (int i = t; i < total; i += gridDim.x * blockDim.x)
        ((unsigned int*)g_hist13)[i] = 0;
    if (t < NBATCH) g_cnt[t] = 0;
}

__global__ void fb_hist(const float4* __restrict__ in, int nvec) {
    if (!g_fail) return;
    __shared__ unsigned int sh[FBBINS];
    const int b = blockIdx.y;
    for (int i = threadIdx.x; i < FBBINS; i += blockDim.x) sh[i] = 0;
    __syncthreads();
    const float4* p = in + (size_t)b * nvec;
    int per_block = (nvec + gridDim.x - 1) / gridDim.x;
    int start = blockIdx.x * per_block;
    int end   = min(start + per_block, nvec);
    for (int i = start + threadIdx.x; i < end; i += blockDim.x) {
        float4 v = p[i];
        atomicAdd(&sh[f2k(v.x) >> 19], 1u);
        atomicAdd(&sh[f2k(v.y) >> 19], 1u);
        atomicAdd(&sh[f2k(v.z) >> 19], 1u);
        atomicAdd(&sh[f2k(v.w) >> 19], 1u);
    }
    __syncthreads();
    for (int i = threadIdx.x; i < FBBINS; i += blockDim.x) {
        unsigned int c = sh[i];
        if (c) atomicAdd(&g_hist13[b][i], c);
    }
}

__global__ void fb_scan(int k) {
    if (!g_fail) return;
    __shared__ unsigned int sh[FBBINS];
    const int b = blockIdx.x;
    for (int i = threadIdx.x; i < FBBINS; i += blockDim.x) sh[i] = g_hist13[b][i];
    __syncthreads();
    if (threadIdx.x == 0) {
        unsigned int cum = 0;
        for (int j = FBBINS - 1; j >= 0; j--) {
            unsigned int c = sh[j];
            if (cum + c >= (unsigned int)k) {
                g_pref[b] = (unsigned int)j;
                g_krem[b] = (unsigned int)k - cum;
                break;
            }
            cum += c;
        }
    }
}

__global__ void fb_cand(const float4* __restrict__ in, int nvec) {
    if (!g_fail) return;
    __shared__ unsigned int s_n, s_base;
    __shared__ unsigned int skey[FSCAP];
    __shared__ unsigned int sidx[FSCAP];
    const int b = blockIdx.y;
    const unsigned int pref = g_pref[b];
    if (threadIdx.x == 0) s_n = 0;
    __syncthreads();
    const float4* p = in + (size_t)b * nvec;
    int per_block = (nvec + gridDim.x - 1) / gridDim.x;
    int start = blockIdx.x * per_block;
    int end   = min(start + per_block, nvec);
    for (int i = start + threadIdx.x; i < end; i += blockDim.x) {
        float4 v = p[i];
        unsigned int kk[4] = { f2k(v.x), f2k(v.y), f2k(v.z), f2k(v.w) };
        #pragma unroll
        for (int j = 0; j < 4; j++) {
            if ((kk[j] >> 19) == pref) {
                unsigned int gi  = (unsigned int)i * 4u + (unsigned int)j;
                unsigned int pos = atomicAdd(&s_n, 1u);
                if (pos < FSCAP) { skey[pos] = kk[j]; sidx[pos] = gi; }
                else {
                    unsigned int gp = atomicAdd(&g_cnt[b], 1u);
                    if (gp < CAP) { g_ckey[b][gp] = kk[j]; g_cidx[b][gp] = gi; }
                }
            }
        }
    }
    __syncthreads();
    if (threadIdx.x == 0) {
        unsigned int m = min(s_n, (unsigned int)FSCAP);
        s_base = atomicAdd(&g_cnt[b], m);
        s_n = m;
    }
    __syncthreads();
    for (unsigned int i = threadIdx.x; i < s_n; i += blockDim.x) {
        unsigned int gp = s_base + i;
        if (gp < CAP) { g_ckey[b][gp] = skey[i]; g_cidx[b][gp] = sidx[i]; }
    }
}

__global__ void fb_select() {
    if (!g_fail) return;
    __shared__ unsigned int hist[256];
    __shared__ unsigned int s_fixedval, s_fixedmask, s_rank, s_E;
    __shared__ unsigned int eq_idx[4096];
    __shared__ unsigned int s_neq, s_cut;
    const int b = blockIdx.x;
    const unsigned int n = min(g_cnt[b], (unsigned int)CAP);
    if (threadIdx.x == 0) {
        s_fixedval = 0; s_fixedmask = 0; s_rank = g_krem[b]; s_E = 0;
        s_neq = 0; s_cut = 0xFFFFFFFFu;
    }
    __syncthreads();
    const int shifts[3] = { 11, 3, 0 };
    const int widths[3] = { 8, 8, 3 };
    for (int r = 0; r < 3; r++) {
        const int s = shifts[r];
        const unsigned int mw = (1u << widths[r]) - 1u;
        for (int i = threadIdx.x; i < 256; i += blockDim.x) hist[i] = 0;
        __syncthreads();
        const unsigned int fm = s_fixedmask, fv = s_fixedval;
        for (unsigned int i = threadIdx.x; i < n; i += blockDim.x) {
            unsigned int low = g_ckey[b][i] & 0x7FFFFu;
            if ((low & fm) == fv) atomicAdd(&hist[(low >> s) & mw], 1u);
        }
        __syncthreads();
        if (threadIdx.x == 0) {
            unsigned int cum = 0, rank = s_rank, sel = 0;
            for (int d = (int)mw; d >= 0; d--) {
                unsigned int c = hist[d];
                if (cum + c >= rank) { sel = (unsigned int)d; s_rank = rank - cum; s_E = c; break; }
                cum += c;
            }
            s_fixedval  |= sel << s;
            s_fixedmask |= mw  << s;
        }
        __syncthreads();
    }
    const unsigned int thr   = (g_pref[b] << 19) | s_fixedval;
    const unsigned int extra = s_rank;
    const unsigned int E     = s_E;
    __syncthreads();
    if (extra < E) {
        for (unsigned int i = threadIdx.x; i < n; i += blockDim.x) {
            if (g_ckey[b][i] == thr) {
                unsigned int pos = atomicAdd(&s_neq, 1u);
                if (pos < 4096) eq_idx[pos] = g_cidx[b][i];
            }
        }
        __syncthreads();
        unsigned int ne = min(s_neq, 4096u);
        for (unsigned int j = threadIdx.x; j < ne; j += blockDim.x) {
            unsigned int me = eq_idx[j], c = 0;
            for (unsigned int t = 0; t < ne; t++) if (eq_idx[t] <= me) c++;
            if (c == extra) s_cut = me;
        }
        __syncthreads();
    }
    if (threadIdx.x == 0) { g_thr[b] = thr; g_cut[b] = s_cut; }
}

// ============================== WRITE ======================================

__global__ void k_write(const float4* __restrict__ in, float4* __restrict__ out,
                        int nvec) {
    const int b = blockIdx.y;
    const unsigned int thr = g_thr[b];
    const unsigned int cut = g_cut[b];
    const float4* p = in  + (size_t)b * nvec;
    float4*       q = out + (size_t)b * nvec;
    int per_block = (nvec + gridDim.x - 1) / gridDim.x;
    int start = blockIdx.x * per_block;
    int end   = min(start + per_block, nvec);
    #pragma unroll 2
    for (int i = start + threadIdx.x; i < end; i += blockDim.x) {
        float4 v = p[i];
        unsigned int base = (unsigned int)i * 4u;
        unsigned int k0 = f2k(v.x), k1 = f2k(v.y), k2 = f2k(v.z), k3 = f2k(v.w);
        float4 o;
        o.x = (k0 > thr || (k0 == thr && base + 0u <= cut)) ? v.x : 0.0f;
        o.y = (k1 > thr || (k1 == thr && base + 1u <= cut)) ? v.y : 0.0f;
        o.z = (k2 > thr || (k2 == thr && base + 2u <= cut)) ? v.z : 0.0f;
        o.w = (k3 > thr || (k3 == thr && base + 3u <= cut)) ? v.w : 0.0f;
        q[i] = o;
    }
    // reset scratch for the next graph replay (no other block touches these)
    if (blockIdx.x == 0 && blockIdx.y == 0) {
        for (int i = threadIdx.x; i < NBATCH * FINE; i += blockDim.x)
            ((unsigned int*)g_fhist)[i] = 0;
        if (threadIdx.x < NBATCH) { g_cnt[threadIdx.x] = 0; g_hi[threadIdx.x] = 0; }
        if (threadIdx.x == 0) g_fail = 0;
    }
}

// ============================== HOST =======================================

extern "C" void kernel_launch(void* const* d_in, const int* in_sizes, int n_in,
                              void* d_out, int out_size) {
    (void)n_in; (void)out_size;
    const int total = in_sizes[0];           // 33,554,432
    const int N     = total / NBATCH;        // 4,194,304
    int k = (int)((double)N * 0.1);          // 419,430
    if (k < 1) k = 1;
    const int nvec = N / 4;                  // 1,048,576 float4 per row

    const float4* in  = (const float4*)d_in[0];
    float4*       out = (float4*)d_out;

    dim3 gA(128, NBATCH);
    dim3 gF(64, NBATCH);

    k_passA  <<<gA, 512>>>(in, nvec);
    k_selectB<<<NBATCH, 256>>>(k);
    fb_zero  <<<64, 256>>>();
    fb_hist  <<<gF, 1024>>>(in, nvec);
    fb_scan  <<<NBATCH, 1024>>>(k);
    fb_cand  <<<gF, 1024>>>(in, nvec);
    fb_select<<<NBATCH, 1024>>>();
    k_write  <<<gA, 512>>>(in, out, nvec);
}